// round 3
// baseline (speedup 1.0000x reference)
#include <cuda_runtime.h>
#include <cuda_bf16.h>
#include <mma.h>
#include <math.h>

using namespace nvcuda;

#define NR 8192            // n = b*p rows
#define DD 512             // feature dim
#define BATCH 2048
#define NCLS 200

// ---------------- scratch (__device__ globals, no allocation) ----------------
__device__ __nv_bfloat16 g_f[(size_t)NR * DD];          // normalized features, bf16 (8 MB)
__device__ float g_prod[(size_t)NR * NR];               // similarity matrix (256 MB)
__device__ double g_ce;
__device__ double g_np;
__device__ unsigned char g_tcls[BATCH];                 // class codes (0..199)

// ---------------- reduction helpers ----------------
template <int BS>
__device__ __forceinline__ float blockReduceSum(float v, float* sbuf) {
#pragma unroll
    for (int o = 16; o > 0; o >>= 1) v += __shfl_xor_sync(0xffffffffu, v, o);
    int w = threadIdx.x >> 5;
    if ((threadIdx.x & 31) == 0) sbuf[w] = v;
    __syncthreads();
    if (w == 0) {
        v = (threadIdx.x < BS / 32) ? sbuf[threadIdx.x] : 0.0f;
#pragma unroll
        for (int o = 16; o > 0; o >>= 1) v += __shfl_xor_sync(0xffffffffu, v, o);
        if (threadIdx.x == 0) sbuf[0] = v;
    }
    __syncthreads();
    float r = sbuf[0];
    __syncthreads();
    return r;
}

template <int BS>
__device__ __forceinline__ float blockReduceMax(float v, float* sbuf) {
#pragma unroll
    for (int o = 16; o > 0; o >>= 1) v = fmaxf(v, __shfl_xor_sync(0xffffffffu, v, o));
    int w = threadIdx.x >> 5;
    if ((threadIdx.x & 31) == 0) sbuf[w] = v;
    __syncthreads();
    if (w == 0) {
        v = (threadIdx.x < BS / 32) ? sbuf[threadIdx.x] : -3.0e38f;
#pragma unroll
        for (int o = 16; o > 0; o >>= 1) v = fmaxf(v, __shfl_xor_sync(0xffffffffu, v, o));
        if (threadIdx.x == 0) sbuf[0] = v;
    }
    __syncthreads();
    float r = sbuf[0];
    __syncthreads();
    return r;
}

// ---------------- kernels ----------------
// Decode targets WITHOUT assuming dtype. We read only the first BATCH 32-bit
// words (safe whether the buffer holds BATCH int32 or BATCH int64 elements).
// If every odd word is zero -> little-endian int64, class = w[2i]... but w[2i]
// for i >= BATCH/2 is beyond the words we may touch for int32. So: detect
// using words [0, BATCH), then decode int64 case reading w[2i] for i < BATCH
// (buffer then truly has 2*BATCH words, safe), else int32 case w[i].
__global__ void decode_targets_kernel(const unsigned int* __restrict__ traw) {
    __shared__ int s_allzero;
    if (threadIdx.x == 0) { s_allzero = 1; g_ce = 0.0; g_np = 0.0; }
    __syncthreads();
    // scan odd words among the first BATCH words
    int nz = 0;
    for (int i = threadIdx.x; i < BATCH / 2; i += blockDim.x)
        if (traw[2 * i + 1] != 0u) nz = 1;
    if (__syncthreads_or(nz)) {  // some odd word nonzero -> int32 layout
        for (int i = threadIdx.x; i < BATCH; i += blockDim.x)
            g_tcls[i] = (unsigned char)traw[i];
    } else {                     // int64 layout (low word holds the value)
        for (int i = threadIdx.x; i < BATCH; i += blockDim.x)
            g_tcls[i] = (unsigned char)traw[2 * i];
    }
}

// one block per row: L2 normalize in fp32, store bf16
__global__ void normalize_kernel(const float* __restrict__ x) {
    __shared__ float sbuf[8];
    int row = blockIdx.x;
    const float* xr = x + (size_t)row * DD;
    float s = 0.0f;
    for (int c = threadIdx.x; c < DD; c += 128) { float v = xr[c]; s += v * v; }
    s = blockReduceSum<128>(s, sbuf);
    float inv = 1.0f / fmaxf(sqrtf(s), 1e-12f);
    for (int c = threadIdx.x; c < DD; c += 128)
        g_f[(size_t)row * DD + c] = __float2bfloat16(xr[c] * inv);
}

// C = f @ f^T  (bf16 inputs, fp32 accum) via wmma 16x16x16
__global__ void gemm_kernel() {
    constexpr int BM = 128, BN = 64, BK = 16;
    __shared__ alignas(16) __nv_bfloat16 As[BM * BK];
    __shared__ alignas(16) __nv_bfloat16 Bs[BN * BK];

    const int tid = threadIdx.x;
    const int bm = blockIdx.y * BM, bn = blockIdx.x * BN;
    const int warp = tid >> 5;
    const int wm = (warp & 3) * 32, wn = (warp >> 2) * 32;

    wmma::fragment<wmma::accumulator, 16, 16, 16, float> acc[2][2];
#pragma unroll
    for (int i = 0; i < 2; i++)
#pragma unroll
        for (int j = 0; j < 2; j++) wmma::fill_fragment(acc[i][j], 0.0f);

    for (int k0 = 0; k0 < DD; k0 += BK) {
        // 128x16 A tile: 256 threads x 8 bf16 (uint4)
        ((uint4*)As)[tid] =
            *((const uint4*)(g_f + (size_t)(bm + (tid >> 1)) * DD + k0 + (tid & 1) * 8));
        // 64x16 B tile: first 128 threads
        if (tid < 128)
            ((uint4*)Bs)[tid] =
                *((const uint4*)(g_f + (size_t)(bn + (tid >> 1)) * DD + k0 + (tid & 1) * 8));
        __syncthreads();

        wmma::fragment<wmma::matrix_a, 16, 16, 16, __nv_bfloat16, wmma::row_major> a[2];
        wmma::fragment<wmma::matrix_b, 16, 16, 16, __nv_bfloat16, wmma::col_major> b[2];
        wmma::load_matrix_sync(a[0], As + (size_t)wm * BK, BK);
        wmma::load_matrix_sync(a[1], As + (size_t)(wm + 16) * BK, BK);
        wmma::load_matrix_sync(b[0], Bs + (size_t)wn * BK, BK);
        wmma::load_matrix_sync(b[1], Bs + (size_t)(wn + 16) * BK, BK);
#pragma unroll
        for (int i = 0; i < 2; i++)
#pragma unroll
            for (int j = 0; j < 2; j++) wmma::mma_sync(acc[i][j], a[i], b[j], acc[i][j]);
        __syncthreads();
    }
#pragma unroll
    for (int i = 0; i < 2; i++)
#pragma unroll
        for (int j = 0; j < 2; j++)
            wmma::store_matrix_sync(
                g_prod + (size_t)(bm + wm + i * 16) * NR + (bn + wn + j * 16),
                acc[i][j], NR, wmma::mem_row_major);
}

// one block per anchor row: E1/E2 sums, then log1p terms; row cached in smem
__global__ void epilogue_kernel() {
    __shared__ float rowv[NR];              // 32 KB
    __shared__ unsigned char scls[BATCH];   // 2 KB class codes
    __shared__ float sbuf[8];
    for (int c = threadIdx.x; c < BATCH; c += 256) scls[c] = g_tcls[c];
    __syncthreads();

    const int i = blockIdx.x;
    const int ti = scls[i >> 2];
    const int pi = i & 3;
    const float* pr = g_prod + (size_t)i * NR;

    float e1 = 0.0f, e2 = 0.0f;
    for (int j = threadIdx.x; j < NR; j += 256) {
        float v = pr[j];
        rowv[j] = v;
        bool sc = (scls[j >> 2] == ti);
        bool sa = ((j & 3) == pi);
        float e = __expf(v);
        if (!(sc && sa)) e1 += e;          // neg set for sasc: everything but sasc
        if (!sc && !sa) e2 += e;           // neg set for sadc/dasc: dadc
    }
    float E1 = blockReduceSum<256>(e1, sbuf);
    float E2 = blockReduceSum<256>(e2, sbuf);

    float local = 0.0f;
    for (int j = threadIdx.x; j < NR; j += 256) {
        bool sc = (scls[j >> 2] == ti);
        bool sa = ((j & 3) == pi);
        if (sc || sa) {                     // union of the three positive masks
            float v = rowv[j];
            float E = (sc && sa) ? E1 : E2;
            local += __logf(fmaf(__expf(-v), E, 1.0f));  // E is O(1e3+): log(1+x) exact enough
        }
    }
    float tot = blockReduceSum<256>(local, sbuf);
    if (threadIdx.x == 0) atomicAdd(&g_np, (double)tot);
}

// CE with label smoothing, one block (64 thr) per sample; target from g_tcls
__global__ void ce_kernel(const float* __restrict__ pred) {
    __shared__ float sbuf[2];
    const int i = blockIdx.x;
    const float* p = pred + (size_t)i * NCLS;
    float m = -3.0e38f, slin = 0.0f;
    for (int c = threadIdx.x; c < NCLS; c += 64) {
        float v = p[c];
        m = fmaxf(m, v);
        slin += v;
    }
    m = blockReduceMax<64>(m, sbuf);
    slin = blockReduceSum<64>(slin, sbuf);
    float se = 0.0f;
    for (int c = threadIdx.x; c < NCLS; c += 64) se += __expf(p[c] - m);
    se = blockReduceSum<64>(se, sbuf);
    if (threadIdx.x == 0) {
        float lse = m + __logf(se);
        int t = (int)g_tcls[i];
        float loss = 0.9f * (lse - p[t]) + 0.1f * (lse - slin / (float)NCLS);
        atomicAdd(&g_ce, (double)loss);
    }
}

__global__ void finalize_kernel(float* out) {
    out[0] = (float)(g_ce / (double)BATCH + 0.5 * (g_np / (double)NR));
}

// ---------------- launch ----------------
extern "C" void kernel_launch(void* const* d_in, const int* in_sizes, int n_in,
                              void* d_out, int out_size) {
    // Identify inputs BY ELEMENT COUNT (robust to metadata ordering):
    //   pred:    2048*200   = 409600  fp32
    //   x_part:  2048*4*512 = 4194304 fp32
    //   targets: 2048       int32 or int64 (decoded on device)
    const float* pred = nullptr;
    const float* x_part = nullptr;
    const unsigned int* traw = nullptr;
    for (int i = 0; i < n_in; i++) {
        if (in_sizes[i] == BATCH * NCLS)      pred   = (const float*)d_in[i];
        else if (in_sizes[i] == NR * DD)      x_part = (const float*)d_in[i];
        else if (in_sizes[i] == BATCH)        traw   = (const unsigned int*)d_in[i];
    }
    float* out = (float*)d_out;

    decode_targets_kernel<<<1, 1024>>>(traw);
    normalize_kernel<<<NR, 128>>>(x_part);
    gemm_kernel<<<dim3(NR / 64, NR / 128), 256>>>();
    ce_kernel<<<BATCH, 64>>>(pred);
    epilogue_kernel<<<NR, 256>>>();
    finalize_kernel<<<1, 1>>>(out);
}

// round 4
// speedup vs baseline: 2.1103x; 2.1103x over previous
#include <cuda_runtime.h>
#include <cuda_bf16.h>
#include <mma.h>
#include <math.h>

using namespace nvcuda;

#define NR 8192            // n = b*p rows
#define DD 512             // feature dim
#define BATCH 2048
#define NCLS 200

// ---------------- scratch (__device__ globals, no allocation) ----------------
__device__ __nv_bfloat16 g_f[(size_t)NR * DD];          // normalized features, bf16 (8 MB)
__device__ float g_prod[(size_t)NR * NR];               // similarity matrix (256 MB)
__device__ double g_ce;
__device__ double g_np;
__device__ unsigned char g_tcls[BATCH];                 // class codes (0..199)

// ---------------- reduction helpers ----------------
template <int BS>
__device__ __forceinline__ float blockReduceSum(float v, float* sbuf) {
#pragma unroll
    for (int o = 16; o > 0; o >>= 1) v += __shfl_xor_sync(0xffffffffu, v, o);
    int w = threadIdx.x >> 5;
    if ((threadIdx.x & 31) == 0) sbuf[w] = v;
    __syncthreads();
    if (w == 0) {
        v = (threadIdx.x < BS / 32) ? sbuf[threadIdx.x] : 0.0f;
#pragma unroll
        for (int o = 16; o > 0; o >>= 1) v += __shfl_xor_sync(0xffffffffu, v, o);
        if (threadIdx.x == 0) sbuf[0] = v;
    }
    __syncthreads();
    float r = sbuf[0];
    __syncthreads();
    return r;
}

template <int BS>
__device__ __forceinline__ float blockReduceMax(float v, float* sbuf) {
#pragma unroll
    for (int o = 16; o > 0; o >>= 1) v = fmaxf(v, __shfl_xor_sync(0xffffffffu, v, o));
    int w = threadIdx.x >> 5;
    if ((threadIdx.x & 31) == 0) sbuf[w] = v;
    __syncthreads();
    if (w == 0) {
        v = (threadIdx.x < BS / 32) ? sbuf[threadIdx.x] : -3.0e38f;
#pragma unroll
        for (int o = 16; o > 0; o >>= 1) v = fmaxf(v, __shfl_xor_sync(0xffffffffu, v, o));
        if (threadIdx.x == 0) sbuf[0] = v;
    }
    __syncthreads();
    float r = sbuf[0];
    __syncthreads();
    return r;
}

// ---------------- targets decode (dtype-agnostic, as in R3) ----------------
__global__ void decode_targets_kernel(const unsigned int* __restrict__ traw) {
    if (threadIdx.x == 0) { g_ce = 0.0; g_np = 0.0; }
    __syncthreads();
    int nz = 0;
    for (int i = threadIdx.x; i < BATCH / 2; i += blockDim.x)
        if (traw[2 * i + 1] != 0u) nz = 1;
    if (__syncthreads_or(nz)) {  // int32 layout
        for (int i = threadIdx.x; i < BATCH; i += blockDim.x)
            g_tcls[i] = (unsigned char)traw[i];
    } else {                     // little-endian int64 layout
        for (int i = threadIdx.x; i < BATCH; i += blockDim.x)
            g_tcls[i] = (unsigned char)traw[2 * i];
    }
}

// one block per row: L2 normalize in fp32, store bf16
__global__ void normalize_kernel(const float* __restrict__ x) {
    __shared__ float sbuf[8];
    int row = blockIdx.x;
    const float* xr = x + (size_t)row * DD;
    float s = 0.0f;
    for (int c = threadIdx.x; c < DD; c += 128) { float v = xr[c]; s += v * v; }
    s = blockReduceSum<128>(s, sbuf);
    float inv = 1.0f / fmaxf(sqrtf(s), 1e-12f);
    for (int c = threadIdx.x; c < DD; c += 128)
        g_f[(size_t)row * DD + c] = __float2bfloat16(xr[c] * inv);
}

// ---------------- symmetric GEMM: upper-triangular 128x128 tiles ----------------
// C = f @ f^T, bf16 in / fp32 out. 2-stage cp.async pipeline, BK=32.
// Off-diagonal tiles are mirrored via col_major stores (exact transpose).
__device__ __forceinline__ void cp_async16(void* smem_dst, const void* gmem_src) {
    unsigned s = (unsigned)__cvta_generic_to_shared(smem_dst);
    asm volatile("cp.async.cg.shared.global [%0], [%1], 16;\n" :: "r"(s), "l"(gmem_src));
}

__global__ void __launch_bounds__(256) gemm_kernel() {
    constexpr int LDS = 40;                 // padded row stride (elements)
    constexpr int NKIT = DD / 32;           // 16 K-iterations
    __shared__ alignas(16) __nv_bfloat16 As[2][128 * LDS];
    __shared__ alignas(16) __nv_bfloat16 Bs[2][128 * LDS];

    // triangular tile decode: blockIdx.x in [0, 2080)
    int idx = blockIdx.x;
    int r = 0;
    while (idx >= 64 - r) { idx -= 64 - r; r++; }
    const int bm = r * 128;
    const int bn = (r + idx) * 128;

    const int tid = threadIdx.x;
    const int warp = tid >> 5;
    const int wm = (warp & 3) * 32;         // 4 warps over M
    const int wn = (warp >> 2) * 64;        // 2 warps over N

    // per-thread load coords: 2 chunks of 16B each per tile per stage
    const int c0 = tid;                      // chunk ids: tid, tid+256 (512 chunks)
    const int row0 = c0 >> 2, col0 = (c0 & 3) * 8;
    const int c1 = tid + 256;
    const int row1 = c1 >> 2, col1 = (c1 & 3) * 8;

    auto load_stage = [&](int k0, int s) {
        const __nv_bfloat16* a0 = g_f + (size_t)(bm + row0) * DD + k0 * 32 + col0;
        const __nv_bfloat16* a1 = g_f + (size_t)(bm + row1) * DD + k0 * 32 + col1;
        const __nv_bfloat16* b0 = g_f + (size_t)(bn + row0) * DD + k0 * 32 + col0;
        const __nv_bfloat16* b1 = g_f + (size_t)(bn + row1) * DD + k0 * 32 + col1;
        cp_async16(&As[s][row0 * LDS + col0], a0);
        cp_async16(&As[s][row1 * LDS + col1], a1);
        cp_async16(&Bs[s][row0 * LDS + col0], b0);
        cp_async16(&Bs[s][row1 * LDS + col1], b1);
    };

    wmma::fragment<wmma::accumulator, 16, 16, 16, float> acc[2][4];
#pragma unroll
    for (int i = 0; i < 2; i++)
#pragma unroll
        for (int j = 0; j < 4; j++) wmma::fill_fragment(acc[i][j], 0.0f);

    load_stage(0, 0);
    asm volatile("cp.async.commit_group;\n");

    for (int k0 = 0; k0 < NKIT; k0++) {
        if (k0 + 1 < NKIT) load_stage(k0 + 1, (k0 + 1) & 1);
        asm volatile("cp.async.commit_group;\n");
        asm volatile("cp.async.wait_group 1;\n");
        __syncthreads();

        const int s = k0 & 1;
#pragma unroll
        for (int kk = 0; kk < 2; kk++) {
            wmma::fragment<wmma::matrix_a, 16, 16, 16, __nv_bfloat16, wmma::row_major> a[2];
            wmma::fragment<wmma::matrix_b, 16, 16, 16, __nv_bfloat16, wmma::col_major> b[4];
#pragma unroll
            for (int i = 0; i < 2; i++)
                wmma::load_matrix_sync(a[i], &As[s][(wm + i * 16) * LDS + kk * 16], LDS);
#pragma unroll
            for (int j = 0; j < 4; j++)
                wmma::load_matrix_sync(b[j], &Bs[s][(wn + j * 16) * LDS + kk * 16], LDS);
#pragma unroll
            for (int i = 0; i < 2; i++)
#pragma unroll
                for (int j = 0; j < 4; j++) wmma::mma_sync(acc[i][j], a[i], b[j], acc[i][j]);
        }
        __syncthreads();
    }

    // store tile (row-major) and, for off-diagonal, its transpose (col-major store)
#pragma unroll
    for (int i = 0; i < 2; i++)
#pragma unroll
        for (int j = 0; j < 4; j++) {
            wmma::store_matrix_sync(
                g_prod + (size_t)(bm + wm + i * 16) * NR + (bn + wn + j * 16),
                acc[i][j], NR, wmma::mem_row_major);
            if (bm != bn)
                wmma::store_matrix_sync(
                    g_prod + (size_t)(bn + wn + j * 16) * NR + (bm + wm + i * 16),
                    acc[i][j], NR, wmma::mem_col_major);
        }
}

// ---------------- epilogue: one block per anchor row ----------------
__global__ void epilogue_kernel() {
    __shared__ float rowv[NR];              // 32 KB
    __shared__ unsigned char scls[BATCH];   // 2 KB class codes
    __shared__ float sbuf[8];
    for (int c = threadIdx.x; c < BATCH; c += 256) scls[c] = g_tcls[c];
    __syncthreads();

    const int i = blockIdx.x;
    const int ti = scls[i >> 2];
    const int pi = i & 3;
    const float* pr = g_prod + (size_t)i * NR;

    float e1 = 0.0f, e2 = 0.0f;
    for (int j = threadIdx.x; j < NR; j += 256) {
        float v = pr[j];
        rowv[j] = v;
        bool sc = (scls[j >> 2] == ti);
        bool sa = ((j & 3) == pi);
        float e = __expf(v);
        if (!(sc && sa)) e1 += e;          // neg set for sasc positives: ~sasc
        if (!sc && !sa) e2 += e;           // neg set for sadc/dasc positives: dadc
    }
    float E1 = blockReduceSum<256>(e1, sbuf);
    float E2 = blockReduceSum<256>(e2, sbuf);

    float local = 0.0f;
    for (int j = threadIdx.x; j < NR; j += 256) {
        bool sc = (scls[j >> 2] == ti);
        bool sa = ((j & 3) == pi);
        if (sc || sa) {                     // union of the three positive masks
            float v = rowv[j];
            float E = (sc && sa) ? E1 : E2;
            local += __logf(fmaf(__expf(-v), E, 1.0f));
        }
    }
    float tot = blockReduceSum<256>(local, sbuf);
    if (threadIdx.x == 0) atomicAdd(&g_np, (double)tot);
}

// CE with label smoothing, one block (64 thr) per sample; target from g_tcls
__global__ void ce_kernel(const float* __restrict__ pred) {
    __shared__ float sbuf[2];
    const int i = blockIdx.x;
    const float* p = pred + (size_t)i * NCLS;
    float m = -3.0e38f, slin = 0.0f;
    for (int c = threadIdx.x; c < NCLS; c += 64) {
        float v = p[c];
        m = fmaxf(m, v);
        slin += v;
    }
    m = blockReduceMax<64>(m, sbuf);
    slin = blockReduceSum<64>(slin, sbuf);
    float se = 0.0f;
    for (int c = threadIdx.x; c < NCLS; c += 64) se += __expf(p[c] - m);
    se = blockReduceSum<64>(se, sbuf);
    if (threadIdx.x == 0) {
        float lse = m + __logf(se);
        int t = (int)g_tcls[i];
        float loss = 0.9f * (lse - p[t]) + 0.1f * (lse - slin / (float)NCLS);
        atomicAdd(&g_ce, (double)loss);
    }
}

__global__ void finalize_kernel(float* out) {
    out[0] = (float)(g_ce / (double)BATCH + 0.5 * (g_np / (double)NR));
}

// ---------------- launch ----------------
extern "C" void kernel_launch(void* const* d_in, const int* in_sizes, int n_in,
                              void* d_out, int out_size) {
    // Identify inputs BY ELEMENT COUNT:
    //   pred:    409600 fp32, x_part: 4194304 fp32, targets: 2048 (int32/int64)
    const float* pred = nullptr;
    const float* x_part = nullptr;
    const unsigned int* traw = nullptr;
    for (int i = 0; i < n_in; i++) {
        if (in_sizes[i] == BATCH * NCLS)      pred   = (const float*)d_in[i];
        else if (in_sizes[i] == NR * DD)      x_part = (const float*)d_in[i];
        else if (in_sizes[i] == BATCH)        traw   = (const unsigned int*)d_in[i];
    }
    float* out = (float*)d_out;

    decode_targets_kernel<<<1, 1024>>>(traw);
    normalize_kernel<<<NR, 128>>>(x_part);
    gemm_kernel<<<2080, 256>>>();           // upper-triangular 128x128 tiles
    ce_kernel<<<BATCH, 64>>>(pred);
    epilogue_kernel<<<NR, 256>>>();
    finalize_kernel<<<1, 1>>>(out);
}